// round 1
// baseline (speedup 1.0000x reference)
#include <cuda_runtime.h>
#include <cuda_bf16.h>
#include <cstdint>

// Problem constants (fixed by the dataset): feats (C=512, N), logits (K=150, N), N = 512*512.
#define C_DIM 512
#define K_DIM 150
#define K_PAD 160          // padded K for tiling (rows >=150 are zero)
#define N_MAX 262144

// ---------------- device scratch (no allocations allowed) ----------------
__device__ float g_probs[(size_t)K_DIM * N_MAX];   // softmax probs, (K, N) layout
__device__ float g_acc[K_DIM * C_DIM];             // unnormalized context accumulator
__device__ float g_S[K_PAD];                       // per-class prob column sums

// ---------------- f32x2 packed-math helpers (FFMA2 only via PTX) ----------------
__device__ __forceinline__ unsigned long long dup2(float x) {
    unsigned long long r;
    unsigned xb = __float_as_uint(x);
    asm("mov.b64 %0, {%1, %1};" : "=l"(r) : "r"(xb));
    return r;
}
__device__ __forceinline__ unsigned long long pack2(float lo, float hi) {
    unsigned long long r;
    asm("mov.b64 %0, {%1, %2};" : "=l"(r) : "r"(__float_as_uint(lo)), "r"(__float_as_uint(hi)));
    return r;
}
__device__ __forceinline__ void ffma2(unsigned long long& d, unsigned long long a, unsigned long long b) {
    asm("fma.rn.f32x2 %0, %1, %2, %3;" : "=l"(d) : "l"(a), "l"(b), "l"(d));
}
__device__ __forceinline__ void unpack2(unsigned long long v, float& lo, float& hi) {
    asm("mov.b64 {%0, %1}, %2;" : "=f"(lo), "=f"(hi) : "l"(v));
}

// ---------------- K0: zero accumulators ----------------
__global__ void zero_kernel() {
    int i = blockIdx.x * blockDim.x + threadIdx.x;
    if (i < K_DIM * C_DIM) g_acc[i] = 0.0f;
    if (i < K_PAD) g_S[i] = 0.0f;
}

// ---------------- K1: per-pixel softmax over classes + column sums ----------------
// One thread per pixel. logits (K, N): for a fixed k, consecutive threads read
// consecutive n -> fully coalesced. 3 passes (max / Z / write) keep register use tiny.
__global__ __launch_bounds__(256) void softmax_kernel(const float* __restrict__ logits, int N) {
    __shared__ float Ssh[K_PAD];
    int tid = threadIdx.x;
    if (tid < K_PAD) Ssh[tid] = 0.0f;
    __syncthreads();

    int n = blockIdx.x * blockDim.x + tid;   // N is a multiple of 256; all valid

    float m = -3.0e38f;
    #pragma unroll 5
    for (int k = 0; k < K_DIM; k++)
        m = fmaxf(m, logits[(size_t)k * N + n]);

    float z = 0.0f;
    #pragma unroll 5
    for (int k = 0; k < K_DIM; k++)
        z += __expf(logits[(size_t)k * N + n] - m);
    float invz = 1.0f / z;

    for (int k = 0; k < K_DIM; k++) {
        float p = __expf(logits[(size_t)k * N + n] - m) * invz;
        g_probs[(size_t)k * N + n] = p;
        // warp reduce -> one smem atomic per warp per k
        #pragma unroll
        for (int o = 16; o; o >>= 1)
            p += __shfl_xor_sync(0xffffffffu, p, o);
        if ((tid & 31) == 0) atomicAdd(&Ssh[k], p);
    }
    __syncthreads();
    if (tid < K_DIM) atomicAdd(&g_S[tid], Ssh[tid]);
}

// ---------------- K2: GEMM  acc[k][c] += sum_n probs[k][n] * feats[c][n] ----------------
// Output tile: 160 (K_PAD) x 128 (C).  Grid: 37 N-splits  x  4 C-tiles = 148 CTAs (1 wave).
// 320 threads, microtile 8(k) x 8(c) per thread, packed f32x2 FMA (FFMA2).
#define NB    32     // n values per staging block
#define SP    164    // Ps row stride (words), pad vs 160 to break store conflicts
#define FP    132    // Fs row stride (words)
#define NSPLIT 37

__global__ __launch_bounds__(320, 1) void gemm_kernel(const float* __restrict__ feats, int N) {
    __shared__ float Ps[NB * SP];   // Ps[nn][k]  : probs, k contiguous
    __shared__ float Fs[NB * FP];   // Fs[nn][c]  : feats, c contiguous

    int t  = threadIdx.x;
    int tx = t & 15;                // 16 c-groups
    int ty = t >> 4;                // 20 k-groups (20*8 = 160)
    int split = blockIdx.x;         // 0..36
    int c0 = blockIdx.y * 128;      // C tile base

    unsigned long long acc[4][8];   // acc[kp][j] holds (k0+2kp, k0+2kp+1) x column j
    #pragma unroll
    for (int i = 0; i < 4; i++)
        #pragma unroll
        for (int j = 0; j < 8; j++) acc[i][j] = 0ull;

    int k0 = ty * 8;
    int nblocks = N / NB;           // 8192

    for (int b = split; b < nblocks; b += NSPLIT) {
        int n0 = b * NB;
        __syncthreads();
        // stage probs tile: 160 x 32 (rows >= 150 zero). Warp covers one k-row -> coalesced.
        #pragma unroll
        for (int idx = t; idx < K_PAD * NB; idx += 320) {
            int k = idx >> 5, nn = idx & 31;
            float v = (k < K_DIM) ? g_probs[(size_t)k * N + n0 + nn] : 0.0f;
            Ps[nn * SP + k] = v;
        }
        // stage feats tile: 128 x 32, coalesced
        for (int idx = t; idx < 128 * NB; idx += 320) {
            int c = idx >> 5, nn = idx & 31;
            Fs[nn * FP + c] = feats[(size_t)(c0 + c) * N + n0 + nn];
        }
        __syncthreads();

        #pragma unroll 4
        for (int nn = 0; nn < NB; nn++) {
            const float* prow = &Ps[nn * SP + k0];
            float4 a0 = *(const float4*)(prow);
            float4 a1 = *(const float4*)(prow + 4);
            // F columns split tx*4 and 64+tx*4 -> conflict-free LDS.128
            const float* frow = &Fs[nn * FP];
            float4 f0 = *(const float4*)(frow + tx * 4);
            float4 f1 = *(const float4*)(frow + 64 + tx * 4);

            unsigned long long P2[4];
            P2[0] = pack2(a0.x, a0.y);
            P2[1] = pack2(a0.z, a0.w);
            P2[2] = pack2(a1.x, a1.y);
            P2[3] = pack2(a1.z, a1.w);

            unsigned long long Fd[8];
            Fd[0] = dup2(f0.x); Fd[1] = dup2(f0.y); Fd[2] = dup2(f0.z); Fd[3] = dup2(f0.w);
            Fd[4] = dup2(f1.x); Fd[5] = dup2(f1.y); Fd[6] = dup2(f1.z); Fd[7] = dup2(f1.w);

            #pragma unroll
            for (int ip = 0; ip < 4; ip++)
                #pragma unroll
                for (int j = 0; j < 8; j++)
                    ffma2(acc[ip][j], P2[ip], Fd[j]);
        }
    }

    // reduce partial tile into global accumulator
    #pragma unroll
    for (int ip = 0; ip < 4; ip++) {
        int k = k0 + 2 * ip;
        #pragma unroll
        for (int j = 0; j < 8; j++) {
            int c = c0 + ((j < 4) ? (tx * 4 + j) : (64 + tx * 4 + (j - 4)));
            float lo, hi;
            unpack2(acc[ip][j], lo, hi);
            if (k < K_DIM)     atomicAdd(&g_acc[k * C_DIM + c], lo);
            if (k + 1 < K_DIM) atomicAdd(&g_acc[(k + 1) * C_DIM + c], hi);
        }
    }
}

// ---------------- K3: finalize  out = acc / max(S, 1e-6) ----------------
__global__ void finalize_kernel(float* __restrict__ out) {
    int idx = blockIdx.x * blockDim.x + threadIdx.x;   // 150 blocks * 512 = 76800 exactly
    int k = idx >> 9;                                  // /512
    float s = g_S[k];
    out[idx] = g_acc[idx] / fmaxf(s, 1e-6f);
}

// ---------------- launch ----------------
extern "C" void kernel_launch(void* const* d_in, const int* in_sizes, int n_in,
                              void* d_out, int out_size) {
    const float* feats  = (const float*)d_in[0];   // (512, H, W)
    const float* logits = (const float*)d_in[1];   // (150, H, W)
    float* out = (float*)d_out;                    // (150, 512)
    int N = in_sizes[0] / C_DIM;                   // H*W

    zero_kernel<<<(K_DIM * C_DIM + 511) / 512, 512>>>();
    softmax_kernel<<<N / 256, 256>>>(logits, N);
    gemm_kernel<<<dim3(NSPLIT, C_DIM / 128), 320>>>(feats, N);
    finalize_kernel<<<K_DIM, 512>>>(out);
}

// round 3
// speedup vs baseline: 3.6045x; 3.6045x over previous
#include <cuda_runtime.h>
#include <cuda_bf16.h>
#include <cstdint>

#define C_DIM 512
#define K_DIM 150
#define K_PAD 160
#define N_MAX 262144

// ---------------- device scratch (zero-initialized; rows 150..159 never written) ----
__device__ __nv_bfloat16 g_probs_hi[(size_t)K_PAD * N_MAX];
__device__ __nv_bfloat16 g_probs_lo[(size_t)K_PAD * N_MAX];
__device__ float g_acc[C_DIM * K_PAD];   // acc[c][k]
__device__ float g_S[K_PAD];

// ---------------- PTX helpers (arch-agnostic: sm_80-level only!) ----------------
__device__ __forceinline__ uint32_t smem_u32(const void* p) {
    uint32_t a;
    asm("{ .reg .u64 t; cvta.to.shared.u64 t, %1; cvt.u32.u64 %0, t; }" : "=r"(a) : "l"(p));
    return a;
}
__device__ __forceinline__ void cp16(uint32_t dst, const void* src) {
    asm volatile("cp.async.ca.shared.global [%0], [%1], 16;" :: "r"(dst), "l"(src) : "memory");
}
#define CP_COMMIT() asm volatile("cp.async.commit_group;" ::: "memory")
#define CP_WAIT1()  asm volatile("cp.async.wait_group 1;" ::: "memory")

#define LDSM_X4(r0, r1, r2, r3, addr) \
    asm volatile("ldmatrix.sync.aligned.m8n8.x4.shared.b16 {%0,%1,%2,%3}, [%4];" \
        : "=r"(r0), "=r"(r1), "=r"(r2), "=r"(r3) : "r"(addr))

#define MMA_BF16(d, a, b) \
    asm volatile("mma.sync.aligned.m16n8k16.row.col.f32.bf16.bf16.f32 " \
        "{%0,%1,%2,%3}, {%4,%5,%6,%7}, {%8,%9}, {%0,%1,%2,%3};" \
        : "+f"((d)[0]), "+f"((d)[1]), "+f"((d)[2]), "+f"((d)[3]) \
        : "r"((a)[0]), "r"((a)[1]), "r"((a)[2]), "r"((a)[3]), "r"((b)[0]), "r"((b)[1]))

// ---------------- K0: zero accumulators ----------------
__global__ void zero_kernel() {
    int i = blockIdx.x * blockDim.x + threadIdx.x;
    if (i < C_DIM * K_PAD) g_acc[i] = 0.0f;
    if (i < K_PAD) g_S[i] = 0.0f;
}

// ---------------- K1: online softmax -> bf16 hi/lo probs + column sums ----------------
__global__ __launch_bounds__(256) void softmax_kernel(const float* __restrict__ logits, int N) {
    __shared__ float Ssh[K_DIM];
    int tid = threadIdx.x;
    if (tid < K_DIM) Ssh[tid] = 0.0f;
    __syncthreads();

    size_t n = (size_t)blockIdx.x * 256 + tid;

    float m = -3.0e38f, z = 0.0f;
    #pragma unroll 5
    for (int k = 0; k < K_DIM; k++) {
        float l = logits[(size_t)k * N + n];
        float m2 = fmaxf(m, l);
        z = z * __expf(m - m2) + __expf(l - m2);
        m = m2;
    }
    float invz = 1.0f / z;

    #pragma unroll 5
    for (int k = 0; k < K_DIM; k++) {
        float l = logits[(size_t)k * N + n];
        float p = __expf(l - m) * invz;
        __nv_bfloat16 h = __float2bfloat16(p);
        g_probs_hi[(size_t)k * N + n] = h;
        g_probs_lo[(size_t)k * N + n] = __float2bfloat16(p - __bfloat162float(h));
        float w = p;
        #pragma unroll
        for (int o = 16; o; o >>= 1) w += __shfl_xor_sync(0xffffffffu, w, o);
        if ((tid & 31) == 0) atomicAdd(&Ssh[k], w);
    }
    __syncthreads();
    if (tid < K_DIM) atomicAdd(&g_S[tid], Ssh[tid]);
}

// ---------------- K2: HMMA GEMM  acc[c][k] += sum_n f[c,n] * p[k,n] ----------------
// Split precision: f = fh + fl, p = ph + pl;  D += fh*ph + fh*pl + fl*ph
// CTA tile M=128 (C) x N=160 (classes), KC=32 per chunk, 3-stage cp.async ring.
#define KC       32
#define SPLITS   37
#define A32_OFF  0        // 128 rows x 144B (f32 staged, padded)
#define AH_OFF   18432    // 128 rows x 80B bf16
#define AL_OFF   28672
#define BH_OFF   38912    // 160 rows x 80B bf16
#define BL_OFF   51712
#define STAGE_B  64512
#define GEMM_SMEM (3 * STAGE_B)   // 193536 bytes

__device__ __forceinline__ void issue_loads(uint32_t sb, const float* __restrict__ feats,
                                            int c0, size_t n0, int tid, int N) {
    #pragma unroll
    for (int i = 0; i < 4; i++) {          // A: 128 rows x 128B = 1024 x 16B
        int idx = tid + i * 256;
        int r = idx >> 3, u = idx & 7;
        cp16(sb + A32_OFF + r * 144 + u * 16,
             (const char*)(feats + (size_t)(c0 + r) * N + n0) + u * 16);
    }
    #pragma unroll
    for (int i = 0; i < 5; i++) {          // B hi+lo: 2 x 160 rows x 64B = 1280 x 16B
        int idx = tid + i * 256;
        int arr = idx >= 640;
        int j = arr ? idx - 640 : idx;
        int r = j >> 2, u = j & 3;
        const __nv_bfloat16* base = arr ? g_probs_lo : g_probs_hi;
        cp16(sb + (arr ? BL_OFF : BH_OFF) + r * 80 + u * 16,
             (const char*)(base + (size_t)r * N + n0) + u * 16);
    }
}

__global__ __launch_bounds__(256, 1) void gemm_kernel(const float* __restrict__ feats, int N) {
    extern __shared__ char smem[];
    uint32_t sb0 = smem_u32(smem);
    int tid = threadIdx.x;
    int lane = tid & 31, wid = tid >> 5;
    int wm = wid & 3, wn = wid >> 2;        // 4 warps along M, 2 along N
    int c0 = blockIdx.y * 128;
    int split = blockIdx.x;
    int total_chunks = N / KC;              // 8192
    int cnt = (total_chunks - split + SPLITS - 1) / SPLITS;

    float acc[2][10][4];
    #pragma unroll
    for (int mf = 0; mf < 2; mf++)
        #pragma unroll
        for (int nf = 0; nf < 10; nf++)
            #pragma unroll
            for (int q = 0; q < 4; q++) acc[mf][nf][q] = 0.0f;

    // prologue: 2 chunks in flight
    if (cnt > 0) issue_loads(sb0 + 0 * STAGE_B, feats, c0, (size_t)split * KC, tid, N);
    CP_COMMIT();
    if (cnt > 1) issue_loads(sb0 + 1 * STAGE_B, feats, c0, (size_t)(split + SPLITS) * KC, tid, N);
    CP_COMMIT();

    // ldmatrix lane offsets (within stage)
    uint32_t a_off[2], b_off[5];
    #pragma unroll
    for (int mf = 0; mf < 2; mf++)
        a_off[mf] = (uint32_t)((wm * 32 + mf * 16 + (lane & 15)) * 80 + (lane >> 4) * 16);
    #pragma unroll
    for (int nfp = 0; nfp < 5; nfp++)
        b_off[nfp] = (uint32_t)((wn * 80 + nfp * 16 + (lane & 7) + ((lane >> 4) & 1) * 8) * 80
                                + ((lane >> 3) & 1) * 16);

    int cr = tid >> 1, cp = tid & 1;        // conversion: row, half

    for (int j = 0; j < cnt; j++) {
        int s = j % 3;
        uint32_t sb = sb0 + (uint32_t)s * STAGE_B;
        CP_WAIT1();                          // chunk j's group complete
        __syncthreads();                     // everyone done with chunk j-1's stage
        if (j + 2 < cnt)
            issue_loads(sb0 + (uint32_t)((j + 2) % 3) * STAGE_B, feats, c0,
                        ((size_t)split + (size_t)(j + 2) * SPLITS) * KC, tid, N);
        CP_COMMIT();                         // always commit (possibly empty group)

        // convert staged A f32 -> bf16 hi/lo in smem
        {
            const char* asrc = smem + s * STAGE_B + A32_OFF + cr * 144 + cp * 64;
            char* dh = smem + s * STAGE_B + AH_OFF + cr * 80 + cp * 32;
            char* dl = smem + s * STAGE_B + AL_OFF + cr * 80 + cp * 32;
            #pragma unroll
            for (int q = 0; q < 4; q++) {
                float4 v = *(const float4*)(asrc + q * 16);
                __nv_bfloat162 h01 = __float22bfloat162_rn(make_float2(v.x, v.y));
                __nv_bfloat162 h23 = __float22bfloat162_rn(make_float2(v.z, v.w));
                __nv_bfloat162 l01 = __float22bfloat162_rn(
                    make_float2(v.x - __bfloat162float(h01.x), v.y - __bfloat162float(h01.y)));
                __nv_bfloat162 l23 = __float22bfloat162_rn(
                    make_float2(v.z - __bfloat162float(h23.x), v.w - __bfloat162float(h23.y)));
                *(uint2*)(dh + q * 8) = make_uint2(*(uint32_t*)&h01, *(uint32_t*)&h23);
                *(uint2*)(dl + q * 8) = make_uint2(*(uint32_t*)&l01, *(uint32_t*)&l23);
            }
        }
        __syncthreads();

        // compute: 2 k16 steps
        #pragma unroll
        for (int k16 = 0; k16 < 2; k16++) {
            uint32_t ko = (uint32_t)k16 * 32;
            uint32_t Ahr[2][4], Alr[2][4];
            #pragma unroll
            for (int mf = 0; mf < 2; mf++) {
                LDSM_X4(Ahr[mf][0], Ahr[mf][1], Ahr[mf][2], Ahr[mf][3], sb + AH_OFF + a_off[mf] + ko);
                LDSM_X4(Alr[mf][0], Alr[mf][1], Alr[mf][2], Alr[mf][3], sb + AL_OFF + a_off[mf] + ko);
            }
            uint32_t Bhr[10][2], Blr[10][2];
            #pragma unroll
            for (int nfp = 0; nfp < 5; nfp++) {
                LDSM_X4(Bhr[2*nfp][0], Bhr[2*nfp][1], Bhr[2*nfp+1][0], Bhr[2*nfp+1][1],
                        sb + BH_OFF + b_off[nfp] + ko);
                LDSM_X4(Blr[2*nfp][0], Blr[2*nfp][1], Blr[2*nfp+1][0], Blr[2*nfp+1][1],
                        sb + BL_OFF + b_off[nfp] + ko);
            }
            #pragma unroll
            for (int mf = 0; mf < 2; mf++)
                #pragma unroll
                for (int nf = 0; nf < 10; nf++) {
                    MMA_BF16(acc[mf][nf], Ahr[mf], Bhr[nf]);
                    MMA_BF16(acc[mf][nf], Ahr[mf], Blr[nf]);
                    MMA_BF16(acc[mf][nf], Alr[mf], Bhr[nf]);
                }
        }
    }

    // epilogue: reduce partials into g_acc
    int g = lane >> 2, tg = lane & 3;
    #pragma unroll
    for (int mf = 0; mf < 2; mf++) {
        #pragma unroll
        for (int nf = 0; nf < 10; nf++) {
            int row = c0 + wm * 32 + mf * 16 + g;
            int col = wn * 80 + nf * 8 + tg * 2;
            atomicAdd(&g_acc[row * K_PAD + col],           acc[mf][nf][0]);
            atomicAdd(&g_acc[row * K_PAD + col + 1],       acc[mf][nf][1]);
            atomicAdd(&g_acc[(row + 8) * K_PAD + col],     acc[mf][nf][2]);
            atomicAdd(&g_acc[(row + 8) * K_PAD + col + 1], acc[mf][nf][3]);
        }
    }
}

// ---------------- K3: finalize  out[k][c] = acc[c][k] / max(S[k], 1e-6) ----------------
__global__ void finalize_kernel(float* __restrict__ out) {
    int k = blockIdx.x, ci = threadIdx.x;
    out[k * C_DIM + ci] = g_acc[ci * K_PAD + k] / fmaxf(g_S[k], 1e-6f);
}

// ---------------- launch ----------------
extern "C" void kernel_launch(void* const* d_in, const int* in_sizes, int n_in,
                              void* d_out, int out_size) {
    const float* feats  = (const float*)d_in[0];   // (512, H, W)
    const float* logits = (const float*)d_in[1];   // (150, H, W)
    float* out = (float*)d_out;                    // (150, 512)
    int N = in_sizes[0] / C_DIM;                   // 262144

    cudaFuncSetAttribute(gemm_kernel, cudaFuncAttributeMaxDynamicSharedMemorySize, GEMM_SMEM);

    zero_kernel<<<(C_DIM * K_PAD + 255) / 256, 256>>>();
    softmax_kernel<<<N / 256, 256>>>(logits, N);
    gemm_kernel<<<dim3(SPLITS, C_DIM / 128), 256, GEMM_SMEM>>>(feats, N);
    finalize_kernel<<<K_DIM, C_DIM>>>(out);
}